// round 6
// baseline (speedup 1.0000x reference)
#include <cuda_runtime.h>
#include <cuda_bf16.h>
#include <cstdint>

#define IN_UNITS 256
#define H1 128
#define H2 64
#define MAX_ROWS 16384

// Edge-kernel smem (per CTA of 4 warps, 32 edges/warp-tile).
// Padded strides: 272=256+16, 144=128+16 -> conflict-free ldmatrix phases.
#define H1_STRIDE 272
#define W2_STRIDE 144
#define OFF_H1HI 0
#define OFF_H1LO (128 * H1_STRIDE)                 // 4 warps x 32 rows
#define OFF_W2HI (2 * 128 * H1_STRIDE)             // 69632
#define OFF_W2LO (OFF_W2HI + 128 * W2_STRIDE)      // 88064
#define OFF_BW   (OFF_W2LO + 128 * W2_STRIDE)      // 106496
#define SMEM_TOTAL (OFF_BW + 64 * 8)               // 107008 -> 2 CTAs/SM

__device__ __align__(16) float g_A[MAX_ROWS * H1];   // drug @ W1_top + b1
__device__ __align__(16) float g_B[MAX_ROWS * H1];   // dis  @ W1_bot

// ---------------------------------------------------------------------------
// Kernel 1 (fused): both per-node layer-1 partials in ONE launch so the two
// halves overlap on the chip. blockIdx < nblkA -> drug/W1_top(+b1) -> g_A,
// else -> dis/W1_bot -> g_B.
// ---------------------------------------------------------------------------
__global__ void __launch_bounds__(256) precompute_fused(
    const float* __restrict__ drug, const float* __restrict__ dis,
    const float* __restrict__ W1, const float* __restrict__ b1,
    float* __restrict__ gA, float* __restrict__ gB,
    int n_drug, int n_dis, int nblkA)
{
    const int isB = (blockIdx.x >= nblkA);
    const float* feat   = isB ? dis : drug;
    const float* W1part = isB ? (W1 + IN_UNITS * H1) : W1;
    float* outPre       = isB ? gB : gA;
    const int nrows     = isB ? n_dis : n_drug;
    const int add_bias  = !isB;
    const int blk       = isB ? (blockIdx.x - nblkA) : blockIdx.x;

    __shared__ float sfeat[16][IN_UNITS];
    const int row0 = blk * 16;
    const int tid  = threadIdx.x;

    const int total4 = 16 * IN_UNITS / 4;
    for (int l = tid; l < total4; l += 256) {
        int r  = l / (IN_UNITS / 4);
        int c4 = l % (IN_UNITS / 4);
        float4 v = make_float4(0.f, 0.f, 0.f, 0.f);
        if (row0 + r < nrows)
            v = ((const float4*)(feat + (size_t)(row0 + r) * IN_UNITS))[c4];
        ((float4*)&sfeat[r][0])[c4] = v;
    }
    __syncthreads();

    const int j  = tid & 127;
    const int rh = tid >> 7;
    float acc[8];
    float bb = add_bias ? b1[j] : 0.f;
#pragma unroll
    for (int i = 0; i < 8; i++) acc[i] = bb;

    for (int k0 = 0; k0 < IN_UNITS; k0 += 8) {
        float w[8];
#pragma unroll
        for (int jj = 0; jj < 8; jj++)
            w[jj] = __ldg(W1part + (k0 + jj) * H1 + j);
#pragma unroll
        for (int jj = 0; jj < 8; jj++)
#pragma unroll
            for (int i = 0; i < 8; i++)
                acc[i] += sfeat[rh * 8 + i][k0 + jj] * w[jj];
    }

#pragma unroll
    for (int i = 0; i < 8; i++) {
        int r = row0 + rh * 8 + i;
        if (r < nrows) outPre[(size_t)r * H1 + j] = acc[i];
    }
}

// ---------------------------------------------------------------------------
// mma.sync / ldmatrix helpers (baseline sm_80+; compile at plain sm_103)
// ---------------------------------------------------------------------------
__device__ __forceinline__ uint32_t smem_u32(const void* p) {
    uint32_t a;
    asm("{ .reg .u64 t; cvta.to.shared.u64 t, %1; cvt.u32.u64 %0, t; }"
        : "=r"(a) : "l"(p));
    return a;
}
__device__ __forceinline__ void ldsm_x4(uint32_t* r, uint32_t a) {
    asm volatile("ldmatrix.sync.aligned.m8n8.x4.shared.b16 {%0,%1,%2,%3}, [%4];"
                 : "=r"(r[0]), "=r"(r[1]), "=r"(r[2]), "=r"(r[3]) : "r"(a));
}
__device__ __forceinline__ void ldsm_x4_t(uint32_t* r, uint32_t a) {
    asm volatile("ldmatrix.sync.aligned.m8n8.x4.trans.shared.b16 {%0,%1,%2,%3}, [%4];"
                 : "=r"(r[0]), "=r"(r[1]), "=r"(r[2]), "=r"(r[3]) : "r"(a));
}
__device__ __forceinline__ void mma_bf16(float* c, const uint32_t* a,
                                         uint32_t b0, uint32_t b1) {
    asm volatile(
        "mma.sync.aligned.m16n8k16.row.col.f32.bf16.bf16.f32 "
        "{%0,%1,%2,%3}, {%4,%5,%6,%7}, {%8,%9}, {%0,%1,%2,%3};"
        : "+f"(c[0]), "+f"(c[1]), "+f"(c[2]), "+f"(c[3])
        : "r"(a[0]), "r"(a[1]), "r"(a[2]), "r"(a[3]), "r"(b0), "r"(b1));
}

// ---------------------------------------------------------------------------
// Kernel 2: per-edge MLP. 128 threads (4 warps), 2 CTAs/SM.
// 32-edge warp-private tiles: B (W2) smem reads amortized 2x vs 16-edge.
// gather (coalesced, lane l = k 4l..4l+3) -> bf16 hi/lo smem -> ldmatrix ->
// 3-term split mma.sync (M=32 as 2 m16 tiles) -> layer-3 dot -> STG.
// ---------------------------------------------------------------------------
__global__ void __launch_bounds__(128, 2) edge_kernel(
    const int* __restrict__ src, const int* __restrict__ dst,
    const float* __restrict__ W2, const float* __restrict__ b2,
    const float* __restrict__ W3, const float* __restrict__ b3,
    float* __restrict__ out, int E, int nwt)
{
    extern __shared__ char smem[];
    const int tid = threadIdx.x, wid = tid >> 5, lid = tid & 31;

    // Stage W2 hi/lo (row-major [k][n], padded rows) + (b2, W3) table
    for (int l = tid; l < H1 * H2; l += 128) {
        const int k = l >> 6, o = l & 63;
        float w = W2[l];
        __nv_bfloat16 hb = __float2bfloat16(w);
        __nv_bfloat16 lb = __float2bfloat16(w - __bfloat162float(hb));
        *(__nv_bfloat16*)(smem + OFF_W2HI + k * W2_STRIDE + o * 2) = hb;
        *(__nv_bfloat16*)(smem + OFF_W2LO + k * W2_STRIDE + o * 2) = lb;
    }
    for (int l = tid; l < H2; l += 128)
        ((float2*)(smem + OFF_BW))[l] = make_float2(b2[l], W3[l]);
    __syncthreads();

    const float b3s = __ldg(b3);
    const uint32_t sb = smem_u32(smem);

    // this warp's private 32 h1 rows
    const uint32_t h1hi = sb + OFF_H1HI + wid * 32 * H1_STRIDE;
    const uint32_t h1lo = sb + OFF_H1LO + wid * 32 * H1_STRIDE;
    char* h1hi_p = smem + OFF_H1HI + wid * 32 * H1_STRIDE;
    char* h1lo_p = smem + OFF_H1LO + wid * 32 * H1_STRIDE;

    // ldmatrix lane->address components
    const uint32_t a_off = (lid & 15) * H1_STRIDE + (lid >> 4) * 16;  // +ks*32
    const uint32_t b_row = ((lid >> 3) & 1) * 8 + (lid & 7);          // +ks*16
    const uint32_t b_nt  = (lid >> 4);                                // 0/1

    const int gw = blockIdx.x * 4 + wid;
    const int gstride = gridDim.x * 4;

    for (int wt = gw; wt < nwt; wt += gstride) {
        const int e0 = wt * 32;

        // ---- gather: 32 rows, lane l covers k = 4l..4l+3 ----
#pragma unroll 4
        for (int i = 0; i < 32; i++) {
            int ei = e0 + i;
            if (ei >= E) ei = E - 1;
            const int s = __ldg(src + ei);
            const int d = __ldg(dst + ei);
            float4 av = *(const float4*)(g_A + (size_t)s * H1 + lid * 4);
            float4 bv = *(const float4*)(g_B + (size_t)d * H1 + lid * 4);
            float x0 = fmaxf(av.x + bv.x, 0.f), x1 = fmaxf(av.y + bv.y, 0.f);
            float x2 = fmaxf(av.z + bv.z, 0.f), x3 = fmaxf(av.w + bv.w, 0.f);

            __nv_bfloat162 h01 = __floats2bfloat162_rn(x0, x1);
            __nv_bfloat162 h23 = __floats2bfloat162_rn(x2, x3);
            uint32_t hb01 = *(uint32_t*)&h01, hb23 = *(uint32_t*)&h23;
            float r0 = x0 - __uint_as_float((hb01 & 0xFFFFu) << 16);
            float r1 = x1 - __uint_as_float(hb01 & 0xFFFF0000u);
            float r2 = x2 - __uint_as_float((hb23 & 0xFFFFu) << 16);
            float r3 = x3 - __uint_as_float(hb23 & 0xFFFF0000u);
            __nv_bfloat162 l01 = __floats2bfloat162_rn(r0, r1);
            __nv_bfloat162 l23 = __floats2bfloat162_rn(r2, r3);

            const uint32_t off = i * H1_STRIDE + lid * 8;
            *(uint2*)(h1hi_p + off) = make_uint2(hb01, hb23);
            *(uint2*)(h1lo_p + off) =
                make_uint2(*(uint32_t*)&l01, *(uint32_t*)&l23);
        }
        __syncwarp();

        // ---- mma: 8 k-steps x 4 n-pairs x 2 m-tiles x 3 split terms ----
        float acc[2][8][4];
#pragma unroll
        for (int mt = 0; mt < 2; mt++)
#pragma unroll
            for (int nt = 0; nt < 8; nt++)
#pragma unroll
                for (int c = 0; c < 4; c++) acc[mt][nt][c] = 0.f;

#pragma unroll
        for (int ks = 0; ks < 8; ks++) {
            uint32_t ah[2][4], al[2][4];
            ldsm_x4(ah[0], h1hi + a_off + ks * 32);
            ldsm_x4(al[0], h1lo + a_off + ks * 32);
            ldsm_x4(ah[1], h1hi + 16 * H1_STRIDE + a_off + ks * 32);
            ldsm_x4(al[1], h1lo + 16 * H1_STRIDE + a_off + ks * 32);
#pragma unroll
            for (int ntp = 0; ntp < 4; ntp++) {
                const uint32_t brow = (ks * 16 + b_row) * W2_STRIDE
                                    + (ntp * 2 + b_nt) * 16;
                uint32_t bh[4], bl[4];
                ldsm_x4_t(bh, sb + OFF_W2HI + brow);
                ldsm_x4_t(bl, sb + OFF_W2LO + brow);
#pragma unroll
                for (int mt = 0; mt < 2; mt++) {
                    mma_bf16(acc[mt][ntp * 2],     ah[mt], bh[0], bh[1]);
                    mma_bf16(acc[mt][ntp * 2],     al[mt], bh[0], bh[1]);
                    mma_bf16(acc[mt][ntp * 2],     ah[mt], bl[0], bl[1]);
                    mma_bf16(acc[mt][ntp * 2 + 1], ah[mt], bh[2], bh[3]);
                    mma_bf16(acc[mt][ntp * 2 + 1], al[mt], bh[2], bh[3]);
                    mma_bf16(acc[mt][ntp * 2 + 1], ah[mt], bl[2], bl[3]);
                }
            }
        }

        // ---- epilogue: relu(h2+b2).W3, quad reduce, store ----
        const float2* bwt = (const float2*)(smem + OFF_BW);
#pragma unroll
        for (int mt = 0; mt < 2; mt++) {
            float pr = 0.f, pr8 = 0.f;
#pragma unroll
            for (int nt = 0; nt < 8; nt++) {
                const int col = nt * 8 + (lid & 3) * 2;
                float2 c0 = bwt[col], c1 = bwt[col + 1];
                pr  += fmaxf(acc[mt][nt][0] + c0.x, 0.f) * c0.y
                     + fmaxf(acc[mt][nt][1] + c1.x, 0.f) * c1.y;
                pr8 += fmaxf(acc[mt][nt][2] + c0.x, 0.f) * c0.y
                     + fmaxf(acc[mt][nt][3] + c1.x, 0.f) * c1.y;
            }
            pr  += __shfl_xor_sync(0xffffffffu, pr, 1);
            pr  += __shfl_xor_sync(0xffffffffu, pr, 2);
            pr8 += __shfl_xor_sync(0xffffffffu, pr8, 1);
            pr8 += __shfl_xor_sync(0xffffffffu, pr8, 2);
            if ((lid & 3) == 0) {
                const int r = e0 + mt * 16 + (lid >> 2);
                if (r < E)     out[r]     = pr + b3s;
                if (r + 8 < E) out[r + 8] = pr8 + b3s;
            }
        }
        __syncwarp();
    }
}

// ---------------------------------------------------------------------------
extern "C" void kernel_launch(void* const* d_in, const int* in_sizes, int n_in,
                              void* d_out, int out_size)
{
    const float* drug = (const float*)d_in[0];
    const float* dis  = (const float*)d_in[1];
    const int*   src  = (const int*)d_in[2];   // int32 (JAX x64 disabled)
    const int*   dst  = (const int*)d_in[3];
    const float* W1   = (const float*)d_in[4];
    const float* b1   = (const float*)d_in[5];
    const float* W2   = (const float*)d_in[6];
    const float* b2   = (const float*)d_in[7];
    const float* W3   = (const float*)d_in[8];
    const float* b3   = (const float*)d_in[9];

    const int n_drug = in_sizes[0] / IN_UNITS;
    const int n_dis  = in_sizes[1] / IN_UNITS;
    const int E      = in_sizes[2];

    float *gA = nullptr, *gB = nullptr;
    cudaGetSymbolAddress((void**)&gA, g_A);
    cudaGetSymbolAddress((void**)&gB, g_B);

    cudaFuncSetAttribute(edge_kernel, cudaFuncAttributeMaxDynamicSharedMemorySize,
                         SMEM_TOTAL);

    const int nblkA = (n_drug + 15) / 16;
    const int nblkB = (n_dis + 15) / 16;
    precompute_fused<<<nblkA + nblkB, 256>>>(drug, dis, W1, b1, gA, gB,
                                             n_drug, n_dis, nblkA);

    const int nwt = (E + 31) / 32;           // 32-edge warp-tiles
    int grid = 296;                          // 2 CTAs/SM
    if (grid > (nwt + 3) / 4) grid = (nwt + 3) / 4;
    edge_kernel<<<grid, 128, SMEM_TOTAL>>>(src, dst, W2, b2, W3, b3,
                                           (float*)d_out, E, nwt);
}

// round 7
// speedup vs baseline: 1.3298x; 1.3298x over previous
#include <cuda_runtime.h>
#include <cuda_fp16.h>
#include <cstdint>

#define IN_UNITS 256
#define H1 128
#define H2 64
#define MAX_ROWS 16384

// Edge-kernel smem (per CTA of 8 warps, 16 edges/warp-tile).
// Padded strides: 272=256+16, 144=128+16 -> conflict-free ldmatrix phases.
#define H1_STRIDE 272
#define W2_STRIDE 144
#define OFF_H1HI 0
#define OFF_H1LO (128 * H1_STRIDE)                 // 34816
#define OFF_W2   (2 * 128 * H1_STRIDE)             // 69632 (single fp16 W2)
#define OFF_BW   (OFF_W2 + 128 * W2_STRIDE)        // 88064
#define SMEM_TOTAL (OFF_BW + 64 * 8)               // 88576 -> 2 CTAs/SM

__device__ __align__(16) float g_A[MAX_ROWS * H1];   // drug @ W1_top + b1
__device__ __align__(16) float g_B[MAX_ROWS * H1];   // dis  @ W1_bot

// ---------------------------------------------------------------------------
// Kernel 1 (fused): both layer-1 partials in ONE launch (halves precompute
// wall time vs two serialized launches — verified R6).
// ---------------------------------------------------------------------------
__global__ void __launch_bounds__(256) precompute_fused(
    const float* __restrict__ drug, const float* __restrict__ dis,
    const float* __restrict__ W1, const float* __restrict__ b1,
    float* __restrict__ gA, float* __restrict__ gB,
    int n_drug, int n_dis, int nblkA)
{
    const int isB = (blockIdx.x >= nblkA);
    const float* feat   = isB ? dis : drug;
    const float* W1part = isB ? (W1 + IN_UNITS * H1) : W1;
    float* outPre       = isB ? gB : gA;
    const int nrows     = isB ? n_dis : n_drug;
    const int add_bias  = !isB;
    const int blk       = isB ? (blockIdx.x - nblkA) : blockIdx.x;

    __shared__ float sfeat[16][IN_UNITS];
    const int row0 = blk * 16;
    const int tid  = threadIdx.x;

    const int total4 = 16 * IN_UNITS / 4;
    for (int l = tid; l < total4; l += 256) {
        int r  = l / (IN_UNITS / 4);
        int c4 = l % (IN_UNITS / 4);
        float4 v = make_float4(0.f, 0.f, 0.f, 0.f);
        if (row0 + r < nrows)
            v = ((const float4*)(feat + (size_t)(row0 + r) * IN_UNITS))[c4];
        ((float4*)&sfeat[r][0])[c4] = v;
    }
    __syncthreads();

    const int j  = tid & 127;
    const int rh = tid >> 7;
    float acc[8];
    float bb = add_bias ? b1[j] : 0.f;
#pragma unroll
    for (int i = 0; i < 8; i++) acc[i] = bb;

    for (int k0 = 0; k0 < IN_UNITS; k0 += 8) {
        float w[8];
#pragma unroll
        for (int jj = 0; jj < 8; jj++)
            w[jj] = __ldg(W1part + (k0 + jj) * H1 + j);
#pragma unroll
        for (int jj = 0; jj < 8; jj++)
#pragma unroll
            for (int i = 0; i < 8; i++)
                acc[i] += sfeat[rh * 8 + i][k0 + jj] * w[jj];
    }

#pragma unroll
    for (int i = 0; i < 8; i++) {
        int r = row0 + rh * 8 + i;
        if (r < nrows) outPre[(size_t)r * H1 + j] = acc[i];
    }
}

// ---------------------------------------------------------------------------
// mma.sync / ldmatrix helpers (baseline sm_80+; compile at plain sm_103)
// ---------------------------------------------------------------------------
__device__ __forceinline__ uint32_t smem_u32(const void* p) {
    uint32_t a;
    asm("{ .reg .u64 t; cvta.to.shared.u64 t, %1; cvt.u32.u64 %0, t; }"
        : "=r"(a) : "l"(p));
    return a;
}
__device__ __forceinline__ void ldsm_x4(uint32_t* r, uint32_t a) {
    asm volatile("ldmatrix.sync.aligned.m8n8.x4.shared.b16 {%0,%1,%2,%3}, [%4];"
                 : "=r"(r[0]), "=r"(r[1]), "=r"(r[2]), "=r"(r[3]) : "r"(a));
}
__device__ __forceinline__ void ldsm_x4_t(uint32_t* r, uint32_t a) {
    asm volatile("ldmatrix.sync.aligned.m8n8.x4.trans.shared.b16 {%0,%1,%2,%3}, [%4];"
                 : "=r"(r[0]), "=r"(r[1]), "=r"(r[2]), "=r"(r[3]) : "r"(a));
}
__device__ __forceinline__ void mma_f16(float* c, const uint32_t* a,
                                        uint32_t b0, uint32_t b1) {
    asm volatile(
        "mma.sync.aligned.m16n8k16.row.col.f32.f16.f16.f32 "
        "{%0,%1,%2,%3}, {%4,%5,%6,%7}, {%8,%9}, {%0,%1,%2,%3};"
        : "+f"(c[0]), "+f"(c[1]), "+f"(c[2]), "+f"(c[3])
        : "r"(a[0]), "r"(a[1]), "r"(a[2]), "r"(a[3]), "r"(b0), "r"(b1));
}

// ---------------------------------------------------------------------------
// Kernel 2: per-edge MLP. 256 threads (8 warps), 2 CTAs/SM -> 16 warps/SM.
// Warp-private 16-edge tiles. fp16 2-term split: A = Ahi + Alo (exact to
// 2^-23), B = fp16(W2) single; D = Ahi*B + Alo*B; dropped A*Blo ~ 2^-12.
// ---------------------------------------------------------------------------
__global__ void __launch_bounds__(256, 2) edge_kernel(
    const int* __restrict__ src, const int* __restrict__ dst,
    const float* __restrict__ W2, const float* __restrict__ b2,
    const float* __restrict__ W3, const float* __restrict__ b3,
    float* __restrict__ out, int E, int nwt)
{
    extern __shared__ char smem[];
    const int tid = threadIdx.x, wid = tid >> 5, lid = tid & 31;

    // Stage W2 (fp16, row-major [k][n], padded rows) + (b2, W3) table
    for (int l = tid; l < H1 * H2; l += 256) {
        const int k = l >> 6, o = l & 63;
        *(__half*)(smem + OFF_W2 + k * W2_STRIDE + o * 2) = __float2half(W2[l]);
    }
    for (int l = tid; l < H2; l += 256)
        ((float2*)(smem + OFF_BW))[l] = make_float2(b2[l], W3[l]);
    __syncthreads();

    const float b3s = __ldg(b3);
    const uint32_t sb = smem_u32(smem);

    // this warp's private 16 h1 rows
    const uint32_t h1hi = sb + OFF_H1HI + wid * 16 * H1_STRIDE;
    const uint32_t h1lo = sb + OFF_H1LO + wid * 16 * H1_STRIDE;
    char* h1hi_p = smem + OFF_H1HI + wid * 16 * H1_STRIDE;
    char* h1lo_p = smem + OFF_H1LO + wid * 16 * H1_STRIDE;

    // ldmatrix lane->address components
    const uint32_t a_off = (lid & 15) * H1_STRIDE + (lid >> 4) * 16;  // +ks*32
    const uint32_t b_row = ((lid >> 3) & 1) * 8 + (lid & 7);          // +ks*16
    const uint32_t b_nt  = (lid >> 4);                                // 0/1

    const int gw = blockIdx.x * 8 + wid;
    const int gstride = gridDim.x * 8;

    for (int wt = gw; wt < nwt; wt += gstride) {
        const int e0 = wt * 16;

        // ---- gather: 16 rows, lane l covers k = 4l..4l+3 (coalesced) ----
#pragma unroll 4
        for (int i = 0; i < 16; i++) {
            int ei = e0 + i;
            if (ei >= E) ei = E - 1;
            const int s = __ldg(src + ei);
            const int d = __ldg(dst + ei);
            float4 av = *(const float4*)(g_A + (size_t)s * H1 + lid * 4);
            float4 bv = *(const float4*)(g_B + (size_t)d * H1 + lid * 4);
            float x0 = fmaxf(av.x + bv.x, 0.f), x1 = fmaxf(av.y + bv.y, 0.f);
            float x2 = fmaxf(av.z + bv.z, 0.f), x3 = fmaxf(av.w + bv.w, 0.f);

            __half2 h01 = __floats2half2_rn(x0, x1);
            __half2 h23 = __floats2half2_rn(x2, x3);
            float r0 = x0 - __half2float(__low2half(h01));
            float r1 = x1 - __half2float(__high2half(h01));
            float r2 = x2 - __half2float(__low2half(h23));
            float r3 = x3 - __half2float(__high2half(h23));
            __half2 l01 = __floats2half2_rn(r0, r1);
            __half2 l23 = __floats2half2_rn(r2, r3);

            const uint32_t off = i * H1_STRIDE + lid * 8;
            *(uint2*)(h1hi_p + off) =
                make_uint2(*(uint32_t*)&h01, *(uint32_t*)&h23);
            *(uint2*)(h1lo_p + off) =
                make_uint2(*(uint32_t*)&l01, *(uint32_t*)&l23);
        }
        __syncwarp();

        // ---- mma: 8 k-steps x 4 n-pairs x 2 split terms ----
        float acc[8][4];
#pragma unroll
        for (int nt = 0; nt < 8; nt++)
#pragma unroll
            for (int c = 0; c < 4; c++) acc[nt][c] = 0.f;

#pragma unroll
        for (int ks = 0; ks < 8; ks++) {
            uint32_t ah[4], al[4];
            ldsm_x4(ah, h1hi + a_off + ks * 32);
            ldsm_x4(al, h1lo + a_off + ks * 32);
#pragma unroll
            for (int ntp = 0; ntp < 4; ntp++) {
                const uint32_t brow = (ks * 16 + b_row) * W2_STRIDE
                                    + (ntp * 2 + b_nt) * 16;
                uint32_t bm[4];
                ldsm_x4_t(bm, sb + OFF_W2 + brow);
                mma_f16(acc[ntp * 2],     ah, bm[0], bm[1]);
                mma_f16(acc[ntp * 2],     al, bm[0], bm[1]);
                mma_f16(acc[ntp * 2 + 1], ah, bm[2], bm[3]);
                mma_f16(acc[ntp * 2 + 1], al, bm[2], bm[3]);
            }
        }

        // ---- epilogue: relu(h2+b2).W3, quad reduce, store ----
        float pr = 0.f, pr8 = 0.f;
        const float2* bwt = (const float2*)(smem + OFF_BW);
#pragma unroll
        for (int nt = 0; nt < 8; nt++) {
            const int col = nt * 8 + (lid & 3) * 2;
            float2 c0 = bwt[col], c1 = bwt[col + 1];
            pr  += fmaxf(acc[nt][0] + c0.x, 0.f) * c0.y
                 + fmaxf(acc[nt][1] + c1.x, 0.f) * c1.y;
            pr8 += fmaxf(acc[nt][2] + c0.x, 0.f) * c0.y
                 + fmaxf(acc[nt][3] + c1.x, 0.f) * c1.y;
        }
        pr  += __shfl_xor_sync(0xffffffffu, pr, 1);
        pr  += __shfl_xor_sync(0xffffffffu, pr, 2);
        pr8 += __shfl_xor_sync(0xffffffffu, pr8, 1);
        pr8 += __shfl_xor_sync(0xffffffffu, pr8, 2);
        if ((lid & 3) == 0) {
            const int r = lid >> 2;
            if (e0 + r < E)     out[e0 + r]     = pr + b3s;
            if (e0 + r + 8 < E) out[e0 + r + 8] = pr8 + b3s;
        }
        __syncwarp();
    }
}

// ---------------------------------------------------------------------------
extern "C" void kernel_launch(void* const* d_in, const int* in_sizes, int n_in,
                              void* d_out, int out_size)
{
    const float* drug = (const float*)d_in[0];
    const float* dis  = (const float*)d_in[1];
    const int*   src  = (const int*)d_in[2];   // int32 (JAX x64 disabled)
    const int*   dst  = (const int*)d_in[3];
    const float* W1   = (const float*)d_in[4];
    const float* b1   = (const float*)d_in[5];
    const float* W2   = (const float*)d_in[6];
    const float* b2   = (const float*)d_in[7];
    const float* W3   = (const float*)d_in[8];
    const float* b3   = (const float*)d_in[9];

    const int n_drug = in_sizes[0] / IN_UNITS;
    const int n_dis  = in_sizes[1] / IN_UNITS;
    const int E      = in_sizes[2];

    float *gA = nullptr, *gB = nullptr;
    cudaGetSymbolAddress((void**)&gA, g_A);
    cudaGetSymbolAddress((void**)&gB, g_B);

    cudaFuncSetAttribute(edge_kernel, cudaFuncAttributeMaxDynamicSharedMemorySize,
                         SMEM_TOTAL);

    const int nblkA = (n_drug + 15) / 16;
    const int nblkB = (n_dis + 15) / 16;
    precompute_fused<<<nblkA + nblkB, 256>>>(drug, dis, W1, b1, gA, gB,
                                             n_drug, n_dis, nblkA);

    const int nwt = (E + 15) / 16;           // 16-edge warp-tiles
    int grid = 296;                          // 2 CTAs/SM
    if (grid > (nwt + 7) / 8) grid = (nwt + 7) / 8;
    edge_kernel<<<grid, 256, SMEM_TOTAL>>>(src, dst, W2, b2, W3, b3,
                                           (float*)d_out, E, nwt);
}

// round 8
// speedup vs baseline: 1.6178x; 1.2166x over previous
#include <cuda_runtime.h>
#include <cuda_fp16.h>
#include <cstdint>

#define IN_UNITS 256
#define H1 128
#define H2 64
#define MAX_ROWS 16384

// Edge-kernel smem (per CTA of 8 warps, 32 edges/warp-tile, single fp16 h1).
// Padded strides: 272=256+16, 144=128+16 -> conflict-free ldmatrix phases.
#define H1_STRIDE 272
#define W2_STRIDE 144
#define OFF_H1   0                                  // 8 warps x 32 rows
#define OFF_W2   (256 * H1_STRIDE)                  // 69632
#define OFF_BW   (OFF_W2 + 128 * W2_STRIDE)         // 88064
#define SMEM_TOTAL (OFF_BW + 64 * 8)                // 88576 -> 2 CTAs/SM

__device__ __align__(16) float g_A[MAX_ROWS * H1];   // drug @ W1_top + b1
__device__ __align__(16) float g_B[MAX_ROWS * H1];   // dis  @ W1_bot

// ---------------------------------------------------------------------------
// Kernel 1 (fused): both layer-1 partials in ONE launch. Inner loop reads
// sfeat via float4 (16 LDS.128 per 8-k block vs 64 scalar LDS) — it was
// issue-bound (37%) in R7.
// ---------------------------------------------------------------------------
__global__ void __launch_bounds__(256) precompute_fused(
    const float* __restrict__ drug, const float* __restrict__ dis,
    const float* __restrict__ W1, const float* __restrict__ b1,
    float* __restrict__ gA, float* __restrict__ gB,
    int n_drug, int n_dis, int nblkA)
{
    const int isB = (blockIdx.x >= nblkA);
    const float* feat   = isB ? dis : drug;
    const float* W1part = isB ? (W1 + IN_UNITS * H1) : W1;
    float* outPre       = isB ? gB : gA;
    const int nrows     = isB ? n_dis : n_drug;
    const int add_bias  = !isB;
    const int blk       = isB ? (blockIdx.x - nblkA) : blockIdx.x;

    __shared__ float sfeat[16][IN_UNITS];
    const int row0 = blk * 16;
    const int tid  = threadIdx.x;

    const int total4 = 16 * IN_UNITS / 4;
    for (int l = tid; l < total4; l += 256) {
        int r  = l / (IN_UNITS / 4);
        int c4 = l % (IN_UNITS / 4);
        float4 v = make_float4(0.f, 0.f, 0.f, 0.f);
        if (row0 + r < nrows)
            v = ((const float4*)(feat + (size_t)(row0 + r) * IN_UNITS))[c4];
        ((float4*)&sfeat[r][0])[c4] = v;
    }
    __syncthreads();

    const int j  = tid & 127;
    const int rh = tid >> 7;
    float acc[8];
    float bb = add_bias ? b1[j] : 0.f;
#pragma unroll
    for (int i = 0; i < 8; i++) acc[i] = bb;

    for (int k0 = 0; k0 < IN_UNITS; k0 += 8) {
        float w[8];
#pragma unroll
        for (int jj = 0; jj < 8; jj++)
            w[jj] = __ldg(W1part + (k0 + jj) * H1 + j);
#pragma unroll
        for (int i = 0; i < 8; i++) {
            float4 f0 = *(const float4*)&sfeat[rh * 8 + i][k0];
            float4 f1 = *(const float4*)&sfeat[rh * 8 + i][k0 + 4];
            acc[i] += f0.x * w[0] + f0.y * w[1] + f0.z * w[2] + f0.w * w[3]
                    + f1.x * w[4] + f1.y * w[5] + f1.z * w[6] + f1.w * w[7];
        }
    }

#pragma unroll
    for (int i = 0; i < 8; i++) {
        int r = row0 + rh * 8 + i;
        if (r < nrows) outPre[(size_t)r * H1 + j] = acc[i];
    }
}

// ---------------------------------------------------------------------------
// mma.sync / ldmatrix helpers (baseline sm_80+; compile at plain sm_103)
// ---------------------------------------------------------------------------
__device__ __forceinline__ uint32_t smem_u32(const void* p) {
    uint32_t a;
    asm("{ .reg .u64 t; cvta.to.shared.u64 t, %1; cvt.u32.u64 %0, t; }"
        : "=r"(a) : "l"(p));
    return a;
}
__device__ __forceinline__ void ldsm_x4(uint32_t* r, uint32_t a) {
    asm volatile("ldmatrix.sync.aligned.m8n8.x4.shared.b16 {%0,%1,%2,%3}, [%4];"
                 : "=r"(r[0]), "=r"(r[1]), "=r"(r[2]), "=r"(r[3]) : "r"(a));
}
__device__ __forceinline__ void ldsm_x4_t(uint32_t* r, uint32_t a) {
    asm volatile("ldmatrix.sync.aligned.m8n8.x4.trans.shared.b16 {%0,%1,%2,%3}, [%4];"
                 : "=r"(r[0]), "=r"(r[1]), "=r"(r[2]), "=r"(r[3]) : "r"(a));
}
__device__ __forceinline__ void mma_f16(float* c, const uint32_t* a,
                                        uint32_t b0, uint32_t b1) {
    asm volatile(
        "mma.sync.aligned.m16n8k16.row.col.f32.f16.f16.f32 "
        "{%0,%1,%2,%3}, {%4,%5,%6,%7}, {%8,%9}, {%0,%1,%2,%3};"
        : "+f"(c[0]), "+f"(c[1]), "+f"(c[2]), "+f"(c[3])
        : "r"(a[0]), "r"(a[1]), "r"(a[2]), "r"(a[3]), "r"(b0), "r"(b1));
}

// ---------------------------------------------------------------------------
// Kernel 2: per-edge MLP. 256 threads (8 warps), 2 CTAs/SM -> 16 warps/SM.
// Warp-private 32-edge tiles, single-pass fp16 (calibrated err ~2^-11).
// B (W2) fragment smem reads amortized over M=32.
// ---------------------------------------------------------------------------
__global__ void __launch_bounds__(256, 2) edge_kernel(
    const int* __restrict__ src, const int* __restrict__ dst,
    const float* __restrict__ W2, const float* __restrict__ b2,
    const float* __restrict__ W3, const float* __restrict__ b3,
    float* __restrict__ out, int E, int nwt)
{
    extern __shared__ char smem[];
    const int tid = threadIdx.x, wid = tid >> 5, lid = tid & 31;

    // Stage W2 (fp16, row-major [k][n], padded rows) + (b2, W3) table
    for (int l = tid; l < H1 * H2; l += 256) {
        const int k = l >> 6, o = l & 63;
        *(__half*)(smem + OFF_W2 + k * W2_STRIDE + o * 2) = __float2half(W2[l]);
    }
    for (int l = tid; l < H2; l += 256)
        ((float2*)(smem + OFF_BW))[l] = make_float2(b2[l], W3[l]);
    __syncthreads();

    const float b3s = __ldg(b3);
    const uint32_t sb = smem_u32(smem);

    // this warp's private 32 h1 rows
    const uint32_t h1s = sb + OFF_H1 + wid * 32 * H1_STRIDE;
    char* h1p = smem + OFF_H1 + wid * 32 * H1_STRIDE;

    // ldmatrix lane->address components
    const uint32_t a_off = (lid & 15) * H1_STRIDE + (lid >> 4) * 16;  // +ks*32
    const uint32_t b_row = ((lid >> 3) & 1) * 8 + (lid & 7);          // +ks*16
    const uint32_t b_nt  = (lid >> 4);                                // 0/1

    const int gw = blockIdx.x * 8 + wid;
    const int gstride = gridDim.x * 8;

    for (int wt = gw; wt < nwt; wt += gstride) {
        const int e0 = wt * 32;

        // ---- gather: 32 rows, lane l covers k = 4l..4l+3 (coalesced) ----
#pragma unroll 4
        for (int i = 0; i < 32; i++) {
            int ei = e0 + i;
            if (ei >= E) ei = E - 1;
            const int s = __ldg(src + ei);
            const int d = __ldg(dst + ei);
            float4 av = *(const float4*)(g_A + (size_t)s * H1 + lid * 4);
            float4 bv = *(const float4*)(g_B + (size_t)d * H1 + lid * 4);
            __half2 h01 = __floats2half2_rn(fmaxf(av.x + bv.x, 0.f),
                                            fmaxf(av.y + bv.y, 0.f));
            __half2 h23 = __floats2half2_rn(fmaxf(av.z + bv.z, 0.f),
                                            fmaxf(av.w + bv.w, 0.f));
            *(uint2*)(h1p + i * H1_STRIDE + lid * 8) =
                make_uint2(*(uint32_t*)&h01, *(uint32_t*)&h23);
        }
        __syncwarp();

        // ---- mma: 8 k-steps x 4 n-pairs x 2 m-tiles, single fp16 pass ----
        float acc[2][8][4];
#pragma unroll
        for (int mt = 0; mt < 2; mt++)
#pragma unroll
            for (int nt = 0; nt < 8; nt++)
#pragma unroll
                for (int c = 0; c < 4; c++) acc[mt][nt][c] = 0.f;

#pragma unroll
        for (int ks = 0; ks < 8; ks++) {
            uint32_t a0[4], a1[4];
            ldsm_x4(a0, h1s + a_off + ks * 32);
            ldsm_x4(a1, h1s + 16 * H1_STRIDE + a_off + ks * 32);
#pragma unroll
            for (int ntp = 0; ntp < 4; ntp++) {
                const uint32_t brow = (ks * 16 + b_row) * W2_STRIDE
                                    + (ntp * 2 + b_nt) * 16;
                uint32_t bm[4];
                ldsm_x4_t(bm, sb + OFF_W2 + brow);
                mma_f16(acc[0][ntp * 2],     a0, bm[0], bm[1]);
                mma_f16(acc[0][ntp * 2 + 1], a0, bm[2], bm[3]);
                mma_f16(acc[1][ntp * 2],     a1, bm[0], bm[1]);
                mma_f16(acc[1][ntp * 2 + 1], a1, bm[2], bm[3]);
            }
        }

        // ---- epilogue: relu(h2+b2).W3, quad reduce, store ----
        const float2* bwt = (const float2*)(smem + OFF_BW);
#pragma unroll
        for (int mt = 0; mt < 2; mt++) {
            float pr = 0.f, pr8 = 0.f;
#pragma unroll
            for (int nt = 0; nt < 8; nt++) {
                const int col = nt * 8 + (lid & 3) * 2;
                float2 c0 = bwt[col], c1 = bwt[col + 1];
                pr  += fmaxf(acc[mt][nt][0] + c0.x, 0.f) * c0.y
                     + fmaxf(acc[mt][nt][1] + c1.x, 0.f) * c1.y;
                pr8 += fmaxf(acc[mt][nt][2] + c0.x, 0.f) * c0.y
                     + fmaxf(acc[mt][nt][3] + c1.x, 0.f) * c1.y;
            }
            pr  += __shfl_xor_sync(0xffffffffu, pr, 1);
            pr  += __shfl_xor_sync(0xffffffffu, pr, 2);
            pr8 += __shfl_xor_sync(0xffffffffu, pr8, 1);
            pr8 += __shfl_xor_sync(0xffffffffu, pr8, 2);
            if ((lid & 3) == 0) {
                const int r = e0 + mt * 16 + (lid >> 2);
                if (r < E)     out[r]     = pr + b3s;
                if (r + 8 < E) out[r + 8] = pr8 + b3s;
            }
        }
        __syncwarp();
    }
}

// ---------------------------------------------------------------------------
extern "C" void kernel_launch(void* const* d_in, const int* in_sizes, int n_in,
                              void* d_out, int out_size)
{
    const float* drug = (const float*)d_in[0];
    const float* dis  = (const float*)d_in[1];
    const int*   src  = (const int*)d_in[2];   // int32 (JAX x64 disabled)
    const int*   dst  = (const int*)d_in[3];
    const float* W1   = (const float*)d_in[4];
    const float* b1   = (const float*)d_in[5];
    const float* W2   = (const float*)d_in[6];
    const float* b2   = (const float*)d_in[7];
    const float* W3   = (const float*)d_in[8];
    const float* b3   = (const float*)d_in[9];

    const int n_drug = in_sizes[0] / IN_UNITS;
    const int n_dis  = in_sizes[1] / IN_UNITS;
    const int E      = in_sizes[2];

    float *gA = nullptr, *gB = nullptr;
    cudaGetSymbolAddress((void**)&gA, g_A);
    cudaGetSymbolAddress((void**)&gB, g_B);

    cudaFuncSetAttribute(edge_kernel, cudaFuncAttributeMaxDynamicSharedMemorySize,
                         SMEM_TOTAL);

    const int nblkA = (n_drug + 15) / 16;
    const int nblkB = (n_dis + 15) / 16;
    precompute_fused<<<nblkA + nblkB, 256>>>(drug, dis, W1, b1, gA, gB,
                                             n_drug, n_dis, nblkA);

    const int nwt = (E + 31) / 32;           // 32-edge warp-tiles
    int grid = 296;                          // 2 CTAs/SM
    if (grid > (nwt + 7) / 8) grid = (nwt + 7) / 8;
    edge_kernel<<<grid, 256, SMEM_TOTAL>>>(src, dst, W2, b2, W3, b3,
                                           (float*)d_out, E, nwt);
}

// round 9
// speedup vs baseline: 1.8394x; 1.1370x over previous
#include <cuda_runtime.h>
#include <cuda_fp16.h>
#include <cstdint>

#define IN_UNITS 256
#define H1 128
#define H2 64
#define MAX_ROWS 16384

// Edge-kernel smem (per CTA of 8 warps, 32 edges/warp-tile, single fp16 h1).
// Padded strides: 272=256+16 (16B-aligned, rows advance 4 banks -> conflict-
// free ldmatrix phases), 144=128+16.
#define H1_STRIDE 272
#define W2_STRIDE 144
#define OFF_H1   0                                  // 8 warps x 32 rows
#define OFF_W2   (256 * H1_STRIDE)                  // 69632
#define OFF_BW   (OFF_W2 + 128 * W2_STRIDE)         // 88064
#define SMEM_TOTAL (OFF_BW + 64 * 8)                // 88576 -> 2 CTAs/SM

// fp16 node partials: 256 B/row -> gather bytes halve vs fp32 (h1 is fp16
// into the MMA anyway; error model calibrated across R5/R7/R8).
__device__ __align__(16) __half g_Ah[MAX_ROWS * H1];  // drug @ W1_top + b1
__device__ __align__(16) __half g_Bh[MAX_ROWS * H1];  // dis  @ W1_bot

// ---------------------------------------------------------------------------
// Kernel 1 (fused): both layer-1 partials in ONE launch; fp16 output.
// ---------------------------------------------------------------------------
__global__ void __launch_bounds__(256) precompute_fused(
    const float* __restrict__ drug, const float* __restrict__ dis,
    const float* __restrict__ W1, const float* __restrict__ b1,
    __half* __restrict__ gA, __half* __restrict__ gB,
    int n_drug, int n_dis, int nblkA)
{
    const int isB = (blockIdx.x >= nblkA);
    const float* feat   = isB ? dis : drug;
    const float* W1part = isB ? (W1 + IN_UNITS * H1) : W1;
    __half* outPre      = isB ? gB : gA;
    const int nrows     = isB ? n_dis : n_drug;
    const int add_bias  = !isB;
    const int blk       = isB ? (blockIdx.x - nblkA) : blockIdx.x;

    __shared__ float sfeat[16][IN_UNITS];
    const int row0 = blk * 16;
    const int tid  = threadIdx.x;

    const int total4 = 16 * IN_UNITS / 4;
    for (int l = tid; l < total4; l += 256) {
        int r  = l / (IN_UNITS / 4);
        int c4 = l % (IN_UNITS / 4);
        float4 v = make_float4(0.f, 0.f, 0.f, 0.f);
        if (row0 + r < nrows)
            v = ((const float4*)(feat + (size_t)(row0 + r) * IN_UNITS))[c4];
        ((float4*)&sfeat[r][0])[c4] = v;
    }
    __syncthreads();

    const int j  = tid & 127;
    const int rh = tid >> 7;
    float acc[8];
    float bb = add_bias ? b1[j] : 0.f;
#pragma unroll
    for (int i = 0; i < 8; i++) acc[i] = bb;

    for (int k0 = 0; k0 < IN_UNITS; k0 += 8) {
        float w[8];
#pragma unroll
        for (int jj = 0; jj < 8; jj++)
            w[jj] = __ldg(W1part + (k0 + jj) * H1 + j);
#pragma unroll
        for (int i = 0; i < 8; i++) {
            float4 f0 = *(const float4*)&sfeat[rh * 8 + i][k0];
            float4 f1 = *(const float4*)&sfeat[rh * 8 + i][k0 + 4];
            acc[i] += f0.x * w[0] + f0.y * w[1] + f0.z * w[2] + f0.w * w[3]
                    + f1.x * w[4] + f1.y * w[5] + f1.z * w[6] + f1.w * w[7];
        }
    }

#pragma unroll
    for (int i = 0; i < 8; i++) {
        int r = row0 + rh * 8 + i;
        if (r < nrows) outPre[(size_t)r * H1 + j] = __float2half_rn(acc[i]);
    }
}

// ---------------------------------------------------------------------------
// mma.sync / ldmatrix helpers (baseline sm_80+; compile at plain sm_103)
// ---------------------------------------------------------------------------
__device__ __forceinline__ uint32_t smem_u32(const void* p) {
    uint32_t a;
    asm("{ .reg .u64 t; cvta.to.shared.u64 t, %1; cvt.u32.u64 %0, t; }"
        : "=r"(a) : "l"(p));
    return a;
}
__device__ __forceinline__ void ldsm_x4(uint32_t* r, uint32_t a) {
    asm volatile("ldmatrix.sync.aligned.m8n8.x4.shared.b16 {%0,%1,%2,%3}, [%4];"
                 : "=r"(r[0]), "=r"(r[1]), "=r"(r[2]), "=r"(r[3]) : "r"(a));
}
__device__ __forceinline__ void ldsm_x4_t(uint32_t* r, uint32_t a) {
    asm volatile("ldmatrix.sync.aligned.m8n8.x4.trans.shared.b16 {%0,%1,%2,%3}, [%4];"
                 : "=r"(r[0]), "=r"(r[1]), "=r"(r[2]), "=r"(r[3]) : "r"(a));
}
__device__ __forceinline__ void mma_f16(float* c, const uint32_t* a,
                                        uint32_t b0, uint32_t b1) {
    asm volatile(
        "mma.sync.aligned.m16n8k16.row.col.f32.f16.f16.f32 "
        "{%0,%1,%2,%3}, {%4,%5,%6,%7}, {%8,%9}, {%0,%1,%2,%3};"
        : "+f"(c[0]), "+f"(c[1]), "+f"(c[2]), "+f"(c[3])
        : "r"(a[0]), "r"(a[1]), "r"(a[2]), "r"(a[3]), "r"(b0), "r"(b1));
}
__device__ __forceinline__ uint32_t hadd2relu(uint32_t a, uint32_t b) {
    __half2 s = __hadd2(*(__half2*)&a, *(__half2*)&b);
    __half2 z = __float2half2_rn(0.f);
    __half2 r = __hmax2(s, z);
    return *(uint32_t*)&r;
}

// ---------------------------------------------------------------------------
// Kernel 2: per-edge MLP. 256 threads (8 warps), 2 CTAs/SM -> 16 warps/SM.
// Warp-private 32-edge tiles. fp16 gather: 2 rows per LDG.128 (16 lanes x
// 16 B = full 256 B row), paired int2 index loads.
// ---------------------------------------------------------------------------
__global__ void __launch_bounds__(256, 2) edge_kernel(
    const int* __restrict__ src, const int* __restrict__ dst,
    const float* __restrict__ W2, const float* __restrict__ b2,
    const float* __restrict__ W3, const float* __restrict__ b3,
    float* __restrict__ out, int E, int nwt)
{
    extern __shared__ char smem[];
    const int tid = threadIdx.x, wid = tid >> 5, lid = tid & 31;

    // Stage W2 (fp16, row-major [k][n], padded rows) + (b2, W3) table
    for (int l = tid; l < H1 * H2; l += 256) {
        const int k = l >> 6, o = l & 63;
        *(__half*)(smem + OFF_W2 + k * W2_STRIDE + o * 2) = __float2half(W2[l]);
    }
    for (int l = tid; l < H2; l += 256)
        ((float2*)(smem + OFF_BW))[l] = make_float2(b2[l], W3[l]);
    __syncthreads();

    const float b3s = __ldg(b3);
    const uint32_t sb = smem_u32(smem);

    // this warp's private 32 h1 rows
    const uint32_t h1s = sb + OFF_H1 + wid * 32 * H1_STRIDE;
    char* h1p = smem + OFF_H1 + wid * 32 * H1_STRIDE;

    // gather lane mapping: half = which of 2 rows, s = 16B chunk in row
    const int half = lid >> 4;
    const int s    = lid & 15;

    // ldmatrix lane->address components
    const uint32_t a_off = (lid & 15) * H1_STRIDE + (lid >> 4) * 16;  // +ks*32
    const uint32_t b_row = ((lid >> 3) & 1) * 8 + (lid & 7);          // +ks*16
    const uint32_t b_nt  = (lid >> 4);                                // 0/1

    const int gw = blockIdx.x * 8 + wid;
    const int gstride = gridDim.x * 8;

    for (int wt = gw; wt < nwt; wt += gstride) {
        const int e0 = wt * 32;

        // ---- gather: 32 rows, 2 rows per iteration ----
#pragma unroll 4
        for (int i2 = 0; i2 < 16; i2++) {
            const int ei0 = e0 + i2 * 2;
            int s0, s1, d0, d1;
            if (ei0 + 1 < E) {
                int2 sp = *(const int2*)(src + ei0);
                int2 dp = *(const int2*)(dst + ei0);
                s0 = sp.x; s1 = sp.y; d0 = dp.x; d1 = dp.y;
            } else {
                int a0 = min(ei0, E - 1), a1 = min(ei0 + 1, E - 1);
                s0 = src[a0]; s1 = src[a1]; d0 = dst[a0]; d1 = dst[a1];
            }
            const int sI = half ? s1 : s0;
            const int dI = half ? d1 : d0;
            const uint4 av = *(const uint4*)(g_Ah + (size_t)sI * H1 + s * 8);
            const uint4 bv = *(const uint4*)(g_Bh + (size_t)dI * H1 + s * 8);
            uint4 hv;
            hv.x = hadd2relu(av.x, bv.x);
            hv.y = hadd2relu(av.y, bv.y);
            hv.z = hadd2relu(av.z, bv.z);
            hv.w = hadd2relu(av.w, bv.w);
            *(uint4*)(h1p + (i2 * 2 + half) * H1_STRIDE + s * 16) = hv;
        }
        __syncwarp();

        // ---- mma: 8 k-steps x 4 n-pairs x 2 m-tiles, single fp16 pass ----
        float acc[2][8][4];
#pragma unroll
        for (int mt = 0; mt < 2; mt++)
#pragma unroll
            for (int nt = 0; nt < 8; nt++)
#pragma unroll
                for (int c = 0; c < 4; c++) acc[mt][nt][c] = 0.f;

#pragma unroll
        for (int ks = 0; ks < 8; ks++) {
            uint32_t a0[4], a1[4];
            ldsm_x4(a0, h1s + a_off + ks * 32);
            ldsm_x4(a1, h1s + 16 * H1_STRIDE + a_off + ks * 32);
#pragma unroll
            for (int ntp = 0; ntp < 4; ntp++) {
                const uint32_t brow = (ks * 16 + b_row) * W2_STRIDE
                                    + (ntp * 2 + b_nt) * 16;
                uint32_t bm[4];
                ldsm_x4_t(bm, sb + OFF_W2 + brow);
                mma_f16(acc[0][ntp * 2],     a0, bm[0], bm[1]);
                mma_f16(acc[0][ntp * 2 + 1], a0, bm[2], bm[3]);
                mma_f16(acc[1][ntp * 2],     a1, bm[0], bm[1]);
                mma_f16(acc[1][ntp * 2 + 1], a1, bm[2], bm[3]);
            }
        }

        // ---- epilogue: relu(h2+b2).W3, quad reduce, store ----
        const float2* bwt = (const float2*)(smem + OFF_BW);
#pragma unroll
        for (int mt = 0; mt < 2; mt++) {
            float pr = 0.f, pr8 = 0.f;
#pragma unroll
            for (int nt = 0; nt < 8; nt++) {
                const int col = nt * 8 + (lid & 3) * 2;
                float2 c0 = bwt[col], c1 = bwt[col + 1];
                pr  += fmaxf(acc[mt][nt][0] + c0.x, 0.f) * c0.y
                     + fmaxf(acc[mt][nt][1] + c1.x, 0.f) * c1.y;
                pr8 += fmaxf(acc[mt][nt][2] + c0.x, 0.f) * c0.y
                     + fmaxf(acc[mt][nt][3] + c1.x, 0.f) * c1.y;
            }
            pr  += __shfl_xor_sync(0xffffffffu, pr, 1);
            pr  += __shfl_xor_sync(0xffffffffu, pr, 2);
            pr8 += __shfl_xor_sync(0xffffffffu, pr8, 1);
            pr8 += __shfl_xor_sync(0xffffffffu, pr8, 2);
            if ((lid & 3) == 0) {
                const int r = e0 + mt * 16 + (lid >> 2);
                if (r < E)     out[r]     = pr + b3s;
                if (r + 8 < E) out[r + 8] = pr8 + b3s;
            }
        }
        __syncwarp();
    }
}

// ---------------------------------------------------------------------------
extern "C" void kernel_launch(void* const* d_in, const int* in_sizes, int n_in,
                              void* d_out, int out_size)
{
    const float* drug = (const float*)d_in[0];
    const float* dis  = (const float*)d_in[1];
    const int*   src  = (const int*)d_in[2];   // int32 (JAX x64 disabled)
    const int*   dst  = (const int*)d_in[3];
    const float* W1   = (const float*)d_in[4];
    const float* b1   = (const float*)d_in[5];
    const float* W2   = (const float*)d_in[6];
    const float* b2   = (const float*)d_in[7];
    const float* W3   = (const float*)d_in[8];
    const float* b3   = (const float*)d_in[9];

    const int n_drug = in_sizes[0] / IN_UNITS;
    const int n_dis  = in_sizes[1] / IN_UNITS;
    const int E      = in_sizes[2];

    __half *gA = nullptr, *gB = nullptr;
    cudaGetSymbolAddress((void**)&gA, g_Ah);
    cudaGetSymbolAddress((void**)&gB, g_Bh);

    cudaFuncSetAttribute(edge_kernel, cudaFuncAttributeMaxDynamicSharedMemorySize,
                         SMEM_TOTAL);

    const int nblkA = (n_drug + 15) / 16;
    const int nblkB = (n_dis + 15) / 16;
    precompute_fused<<<nblkA + nblkB, 256>>>(drug, dis, W1, b1, gA, gB,
                                             n_drug, n_dis, nblkA);

    const int nwt = (E + 31) / 32;           // 32-edge warp-tiles
    int grid = 296;                          // 2 CTAs/SM
    if (grid > (nwt + 7) / 8) grid = (nwt + 7) / 8;
    edge_kernel<<<grid, 256, SMEM_TOTAL>>>(src, dst, W2, b2, W3, b3,
                                           (float*)d_out, E, nwt);
}

// round 10
// speedup vs baseline: 2.5311x; 1.3760x over previous
#include <cuda_runtime.h>
#include <cuda_fp16.h>
#include <cstdint>

#define IN_UNITS 256
#define H1 128
#define H2 64
#define MAX_ROWS 16384

// ---- Edge-kernel smem (unchanged from R9; proven) ----
#define H1_STRIDE 272
#define W2_STRIDE 144
#define OFF_H1   0
#define OFF_W2   (256 * H1_STRIDE)                  // 69632
#define OFF_BW   (OFF_W2 + 128 * W2_STRIDE)         // 88064
#define SMEM_TOTAL (OFF_BW + 64 * 8)                // 88576 -> 2 CTAs/SM

// ---- Precompute-kernel smem (tensor-core GEMM) ----
// W1 half fp16 [k=256][n=128], stride 272 (256+16 -> conflict-free ldsm_t)
// feat fp16 [row=128][k=256], stride 528 (512+16 -> conflict-free ldsm)
#define PRE_W1    0
#define PRE_FEAT  (256 * 272)                       // 69632
#define PRE_B1    (PRE_FEAT + 128 * 528)            // 137216
#define PRE_SMEM  (PRE_B1 + 128 * 4)                // 137728 -> 1 CTA/SM

// fp16 node partials (gather bytes halved; error model calibrated R5/7/8/9)
__device__ __align__(16) __half g_Ah[MAX_ROWS * H1];  // drug @ W1_top + b1
__device__ __align__(16) __half g_Bh[MAX_ROWS * H1];  // dis  @ W1_bot

// ---------------------------------------------------------------------------
// mma.sync / ldmatrix helpers (baseline sm_80+; compile at plain sm_103)
// ---------------------------------------------------------------------------
__device__ __forceinline__ uint32_t smem_u32(const void* p) {
    uint32_t a;
    asm("{ .reg .u64 t; cvta.to.shared.u64 t, %1; cvt.u32.u64 %0, t; }"
        : "=r"(a) : "l"(p));
    return a;
}
__device__ __forceinline__ void ldsm_x4(uint32_t* r, uint32_t a) {
    asm volatile("ldmatrix.sync.aligned.m8n8.x4.shared.b16 {%0,%1,%2,%3}, [%4];"
                 : "=r"(r[0]), "=r"(r[1]), "=r"(r[2]), "=r"(r[3]) : "r"(a));
}
__device__ __forceinline__ void ldsm_x4_t(uint32_t* r, uint32_t a) {
    asm volatile("ldmatrix.sync.aligned.m8n8.x4.trans.shared.b16 {%0,%1,%2,%3}, [%4];"
                 : "=r"(r[0]), "=r"(r[1]), "=r"(r[2]), "=r"(r[3]) : "r"(a));
}
__device__ __forceinline__ void mma_f16(float* c, const uint32_t* a,
                                        uint32_t b0, uint32_t b1) {
    asm volatile(
        "mma.sync.aligned.m16n8k16.row.col.f32.f16.f16.f32 "
        "{%0,%1,%2,%3}, {%4,%5,%6,%7}, {%8,%9}, {%0,%1,%2,%3};"
        : "+f"(c[0]), "+f"(c[1]), "+f"(c[2]), "+f"(c[3])
        : "r"(a[0]), "r"(a[1]), "r"(a[2]), "r"(a[3]), "r"(b0), "r"(b1));
}
__device__ __forceinline__ uint32_t hadd2relu(uint32_t a, uint32_t b) {
    __half2 s = __hadd2(*(__half2*)&a, *(__half2*)&b);
    __half2 z = __float2half2_rn(0.f);
    __half2 r = __hmax2(s, z);
    return *(uint32_t*)&r;
}

// ---------------------------------------------------------------------------
// Kernel 1: layer-1 partials as fp16 tensor-core GEMM.
// CTA = 128 node rows (8 warps x m16), N=128, K=256. blockIdx < nblkA -> drug
// half (+b1) -> g_Ah, else dis half -> g_Bh.
// ---------------------------------------------------------------------------
__global__ void __launch_bounds__(256, 1) precompute_mma(
    const float* __restrict__ drug, const float* __restrict__ dis,
    const float* __restrict__ W1, const float* __restrict__ b1,
    __half* __restrict__ gA, __half* __restrict__ gB,
    int n_drug, int n_dis, int nblkA)
{
    extern __shared__ char smem[];
    const int tid = threadIdx.x, wid = tid >> 5, lid = tid & 31;

    const int isB = (blockIdx.x >= nblkA);
    const float* feat   = isB ? dis : drug;
    const float* W1part = isB ? (W1 + IN_UNITS * H1) : W1;
    __half* outPre      = isB ? gB : gA;
    const int nrows     = isB ? n_dis : n_drug;
    const int blk       = isB ? (blockIdx.x - nblkA) : blockIdx.x;
    const int row0      = blk * 128;

    // Stage W1part fp16 [k][n] (8192 float4, coalesced over n)
    for (int l = tid; l < 8192; l += 256) {
        const int k = l >> 5, o4 = l & 31;           // o4: 4 floats
        float4 v = *(const float4*)(W1part + k * H1 + o4 * 4);
        __half2 h0 = __floats2half2_rn(v.x, v.y);
        __half2 h1 = __floats2half2_rn(v.z, v.w);
        *(uint2*)(smem + PRE_W1 + k * 272 + o4 * 8) =
            make_uint2(*(uint32_t*)&h0, *(uint32_t*)&h1);
    }
    // Stage 128 feat rows fp16 [row][k] (zero-pad beyond nrows)
    for (int l = tid; l < 8192; l += 256) {
        const int r = l >> 6, c4 = l & 63;           // c4: 4 floats
        float4 v = make_float4(0.f, 0.f, 0.f, 0.f);
        if (row0 + r < nrows)
            v = *(const float4*)(feat + (size_t)(row0 + r) * IN_UNITS + c4 * 4);
        __half2 h0 = __floats2half2_rn(v.x, v.y);
        __half2 h1 = __floats2half2_rn(v.z, v.w);
        *(uint2*)(smem + PRE_FEAT + r * 528 + c4 * 8) =
            make_uint2(*(uint32_t*)&h0, *(uint32_t*)&h1);
    }
    if (tid < 128) ((float*)(smem + PRE_B1))[tid] = isB ? 0.f : b1[tid];
    __syncthreads();

    const uint32_t sb = smem_u32(smem);
    const uint32_t fw = sb + PRE_FEAT + wid * 16 * 528;   // warp's 16 rows
    const uint32_t a_off = (lid & 15) * 528 + (lid >> 4) * 16;  // +ks*32
    const uint32_t b_row = ((lid >> 3) & 1) * 8 + (lid & 7);    // +ks*16
    const uint32_t b_nt  = (lid >> 4);

    float acc[16][4];
#pragma unroll
    for (int nt = 0; nt < 16; nt++)
#pragma unroll
        for (int c = 0; c < 4; c++) acc[nt][c] = 0.f;

#pragma unroll 4
    for (int ks = 0; ks < 16; ks++) {
        uint32_t am[4];
        ldsm_x4(am, fw + a_off + ks * 32);
#pragma unroll
        for (int np = 0; np < 8; np++) {
            const uint32_t brow = (ks * 16 + b_row) * 272 + (np * 2 + b_nt) * 16;
            uint32_t bm[4];
            ldsm_x4_t(bm, sb + PRE_W1 + brow);
            mma_f16(acc[np * 2],     am, bm[0], bm[1]);
            mma_f16(acc[np * 2 + 1], am, bm[2], bm[3]);
        }
    }

    // Epilogue: +b1 (drug half), fp16 store straight from fragments
    const float* b1s = (const float*)(smem + PRE_B1);
    const int r  = lid >> 2;
    const int c2 = (lid & 3) * 2;
#pragma unroll
    for (int nt = 0; nt < 16; nt++) {
        const int col = nt * 8 + c2;
        const float bx = b1s[col], by = b1s[col + 1];
        const int ra = row0 + wid * 16 + r;
        if (ra < nrows) {
            __half2 v = __floats2half2_rn(acc[nt][0] + bx, acc[nt][1] + by);
            *(__half2*)(outPre + (size_t)ra * H1 + col) = v;
        }
        const int rb = ra + 8;
        if (rb < nrows) {
            __half2 v = __floats2half2_rn(acc[nt][2] + bx, acc[nt][3] + by);
            *(__half2*)(outPre + (size_t)rb * H1 + col) = v;
        }
    }
}

// ---------------------------------------------------------------------------
// Kernel 2: per-edge MLP (unchanged from R9 — 82us, L1-bound, proven).
// ---------------------------------------------------------------------------
__global__ void __launch_bounds__(256, 2) edge_kernel(
    const int* __restrict__ src, const int* __restrict__ dst,
    const float* __restrict__ W2, const float* __restrict__ b2,
    const float* __restrict__ W3, const float* __restrict__ b3,
    float* __restrict__ out, int E, int nwt)
{
    extern __shared__ char smem[];
    const int tid = threadIdx.x, wid = tid >> 5, lid = tid & 31;

    for (int l = tid; l < H1 * H2; l += 256) {
        const int k = l >> 6, o = l & 63;
        *(__half*)(smem + OFF_W2 + k * W2_STRIDE + o * 2) = __float2half(W2[l]);
    }
    for (int l = tid; l < H2; l += 256)
        ((float2*)(smem + OFF_BW))[l] = make_float2(b2[l], W3[l]);
    __syncthreads();

    const float b3s = __ldg(b3);
    const uint32_t sb = smem_u32(smem);

    const uint32_t h1s = sb + OFF_H1 + wid * 32 * H1_STRIDE;
    char* h1p = smem + OFF_H1 + wid * 32 * H1_STRIDE;

    const int half = lid >> 4;
    const int s    = lid & 15;

    const uint32_t a_off = (lid & 15) * H1_STRIDE + (lid >> 4) * 16;
    const uint32_t b_row = ((lid >> 3) & 1) * 8 + (lid & 7);
    const uint32_t b_nt  = (lid >> 4);

    const int gw = blockIdx.x * 8 + wid;
    const int gstride = gridDim.x * 8;

    for (int wt = gw; wt < nwt; wt += gstride) {
        const int e0 = wt * 32;

#pragma unroll 4
        for (int i2 = 0; i2 < 16; i2++) {
            const int ei0 = e0 + i2 * 2;
            int s0, s1, d0, d1;
            if (ei0 + 1 < E) {
                int2 sp = *(const int2*)(src + ei0);
                int2 dp = *(const int2*)(dst + ei0);
                s0 = sp.x; s1 = sp.y; d0 = dp.x; d1 = dp.y;
            } else {
                int a0 = min(ei0, E - 1), a1 = min(ei0 + 1, E - 1);
                s0 = src[a0]; s1 = src[a1]; d0 = dst[a0]; d1 = dst[a1];
            }
            const int sI = half ? s1 : s0;
            const int dI = half ? d1 : d0;
            const uint4 av = *(const uint4*)(g_Ah + (size_t)sI * H1 + s * 8);
            const uint4 bv = *(const uint4*)(g_Bh + (size_t)dI * H1 + s * 8);
            uint4 hv;
            hv.x = hadd2relu(av.x, bv.x);
            hv.y = hadd2relu(av.y, bv.y);
            hv.z = hadd2relu(av.z, bv.z);
            hv.w = hadd2relu(av.w, bv.w);
            *(uint4*)(h1p + (i2 * 2 + half) * H1_STRIDE + s * 16) = hv;
        }
        __syncwarp();

        float acc[2][8][4];
#pragma unroll
        for (int mt = 0; mt < 2; mt++)
#pragma unroll
            for (int nt = 0; nt < 8; nt++)
#pragma unroll
                for (int c = 0; c < 4; c++) acc[mt][nt][c] = 0.f;

#pragma unroll
        for (int ks = 0; ks < 8; ks++) {
            uint32_t a0[4], a1[4];
            ldsm_x4(a0, h1s + a_off + ks * 32);
            ldsm_x4(a1, h1s + 16 * H1_STRIDE + a_off + ks * 32);
#pragma unroll
            for (int ntp = 0; ntp < 4; ntp++) {
                const uint32_t brow = (ks * 16 + b_row) * W2_STRIDE
                                    + (ntp * 2 + b_nt) * 16;
                uint32_t bm[4];
                ldsm_x4_t(bm, sb + OFF_W2 + brow);
                mma_f16(acc[0][ntp * 2],     a0, bm[0], bm[1]);
                mma_f16(acc[0][ntp * 2 + 1], a0, bm[2], bm[3]);
                mma_f16(acc[1][ntp * 2],     a1, bm[0], bm[1]);
                mma_f16(acc[1][ntp * 2 + 1], a1, bm[2], bm[3]);
            }
        }

        const float2* bwt = (const float2*)(smem + OFF_BW);
#pragma unroll
        for (int mt = 0; mt < 2; mt++) {
            float pr = 0.f, pr8 = 0.f;
#pragma unroll
            for (int nt = 0; nt < 8; nt++) {
                const int col = nt * 8 + (lid & 3) * 2;
                float2 c0 = bwt[col], c1 = bwt[col + 1];
                pr  += fmaxf(acc[mt][nt][0] + c0.x, 0.f) * c0.y
                     + fmaxf(acc[mt][nt][1] + c1.x, 0.f) * c1.y;
                pr8 += fmaxf(acc[mt][nt][2] + c0.x, 0.f) * c0.y
                     + fmaxf(acc[mt][nt][3] + c1.x, 0.f) * c1.y;
            }
            pr  += __shfl_xor_sync(0xffffffffu, pr, 1);
            pr  += __shfl_xor_sync(0xffffffffu, pr, 2);
            pr8 += __shfl_xor_sync(0xffffffffu, pr8, 1);
            pr8 += __shfl_xor_sync(0xffffffffu, pr8, 2);
            if ((lid & 3) == 0) {
                const int r = e0 + mt * 16 + (lid >> 2);
                if (r < E)     out[r]     = pr + b3s;
                if (r + 8 < E) out[r + 8] = pr8 + b3s;
            }
        }
        __syncwarp();
    }
}

// ---------------------------------------------------------------------------
extern "C" void kernel_launch(void* const* d_in, const int* in_sizes, int n_in,
                              void* d_out, int out_size)
{
    const float* drug = (const float*)d_in[0];
    const float* dis  = (const float*)d_in[1];
    const int*   src  = (const int*)d_in[2];   // int32 (JAX x64 disabled)
    const int*   dst  = (const int*)d_in[3];
    const float* W1   = (const float*)d_in[4];
    const float* b1   = (const float*)d_in[5];
    const float* W2   = (const float*)d_in[6];
    const float* b2   = (const float*)d_in[7];
    const float* W3   = (const float*)d_in[8];
    const float* b3   = (const float*)d_in[9];

    const int n_drug = in_sizes[0] / IN_UNITS;
    const int n_dis  = in_sizes[1] / IN_UNITS;
    const int E      = in_sizes[2];

    __half *gA = nullptr, *gB = nullptr;
    cudaGetSymbolAddress((void**)&gA, g_Ah);
    cudaGetSymbolAddress((void**)&gB, g_Bh);

    cudaFuncSetAttribute(precompute_mma,
                         cudaFuncAttributeMaxDynamicSharedMemorySize, PRE_SMEM);
    cudaFuncSetAttribute(edge_kernel,
                         cudaFuncAttributeMaxDynamicSharedMemorySize, SMEM_TOTAL);

    const int nblkA = (n_drug + 127) / 128;
    const int nblkB = (n_dis + 127) / 128;
    precompute_mma<<<nblkA + nblkB, 256, PRE_SMEM>>>(drug, dis, W1, b1, gA, gB,
                                                     n_drug, n_dis, nblkA);

    const int nwt = (E + 31) / 32;           // 32-edge warp-tiles
    int grid = 296;                          // 2 CTAs/SM
    if (grid > (nwt + 7) / 8) grid = (nwt + 7) / 8;
    edge_kernel<<<grid, 256, SMEM_TOTAL>>>(src, dst, W2, b2, W3, b3,
                                           (float*)d_out, E, nwt);
}